// round 4
// baseline (speedup 1.0000x reference)
#include <cuda_runtime.h>
#include <math.h>

#define TDIM 600
#define BATCH 32
#define NBUF (BATCH*128*TDIM)
#define PLANE (16*TDIM)
#define PSLOT (BATCH*PLANE)

__device__ __align__(1024) float g_sp[NBUF];
__device__ __align__(1024) float g_o1[NBUF];
__device__ __align__(1024) float g_o2[NBUF];
__device__ __align__(1024) float g_o3[NBUF];
__device__ __align__(1024) float g_pl[35*PSLOT];
__device__ float g_se[BATCH*128];
__device__ float g_pool[BATCH*1024];

__global__ __launch_bounds__(256) void k_gemm(
    const float* __restrict__ W, const float* __restrict__ bias,
    const float* __restrict__ bn,
    const float* __restrict__ inA, long long aStr,
    const float* __restrict__ inB, long long bStr,
    const float* __restrict__ tail, int kTail,
    float* __restrict__ out)
{
    __shared__ float Ws[32][132];
    __shared__ float Bs[32][68];
    __shared__ float sA[128], sBb[128], sBi[128];
    const int b = blockIdx.y, t0 = blockIdx.x*64, tid = threadIdx.x;

    if (tid < 128) {
        float g=bn[tid], be=bn[128+tid], mm=bn[256+tid], vv=bn[384+tid];
        float a = g*rsqrtf(vv+1e-5f);
        sA[tid]=a; sBb[tid]=be-mm*a; sBi[tid]=bias[tid];
    }
    const float* pA = inA + (long long)b*aStr;
    const float* pB = inB ? inB + (long long)b*bStr : nullptr;
    const float* pT = tail ? tail + (long long)b*(128*TDIM) : nullptr;

    float acc[8][4];
    #pragma unroll
    for (int r=0;r<8;++r){ acc[r][0]=acc[r][1]=acc[r][2]=acc[r][3]=0.f; }
    const int tx = tid&15, ty = tid>>4;
    const int cBase = tx*4, rBase = ty*8;

    for (int k0=0;k0<128;k0+=32){
        __syncthreads();
        #pragma unroll
        for (int it=0;it<4;++it){
            int idx=it*256+tid, mo=idx>>3, kg=(idx&7)<<2;
            float4 w4 = *reinterpret_cast<const float4*>(W + mo*128 + k0 + kg);
            Ws[kg+0][mo]=w4.x; Ws[kg+1][mo]=w4.y; Ws[kg+2][mo]=w4.z; Ws[kg+3][mo]=w4.w;
        }
        #pragma unroll
        for (int it=0;it<2;++it){
            int idx=it*256+tid, kk=idx>>4, cg=(idx&15)<<2;
            int k=k0+kk, t=t0+cg;
            const float* src = (k>=kTail)? (pT + k*TDIM) : (pA + (long long)k*TDIM);
            bool addB = pB && (k<kTail);
            float4 v4;
            if (t+3 < TDIM){
                v4 = *reinterpret_cast<const float4*>(src + t);
                if (addB){
                    float4 u = *reinterpret_cast<const float4*>(pB + (long long)k*TDIM + t);
                    v4.x+=u.x; v4.y+=u.y; v4.z+=u.z; v4.w+=u.w;
                }
            } else {
                float tmp[4];
                #pragma unroll
                for (int q=0;q<4;++q){
                    int tt=t+q; float xv=0.f;
                    if (tt<TDIM){ xv=src[tt]; if(addB) xv+=pB[(long long)k*TDIM+tt]; }
                    tmp[q]=xv;
                }
                v4 = make_float4(tmp[0],tmp[1],tmp[2],tmp[3]);
            }
            *reinterpret_cast<float4*>(&Bs[kk][cg]) = v4;
        }
        __syncthreads();
        #pragma unroll
        for (int kk=0;kk<32;++kk){
            float4 a0=*reinterpret_cast<const float4*>(&Ws[kk][rBase]);
            float4 a1=*reinterpret_cast<const float4*>(&Ws[kk][rBase+4]);
            float4 bv=*reinterpret_cast<const float4*>(&Bs[kk][cBase]);
            float av[8]={a0.x,a0.y,a0.z,a0.w,a1.x,a1.y,a1.z,a1.w};
            float bb[4]={bv.x,bv.y,bv.z,bv.w};
            #pragma unroll
            for (int r=0;r<8;++r)
                #pragma unroll
                for (int q=0;q<4;++q)
                    acc[r][q]=fmaf(av[r],bb[q],acc[r][q]);
        }
    }
    if (t0+cBase+3 < TDIM){
        float* po = out + ((long long)b*128 + rBase)*TDIM + t0 + cBase;
        #pragma unroll
        for (int r=0;r<8;++r){
            int o=rBase+r; float a=sA[o], c2=sBb[o], bi=sBi[o];
            float4 v4;
            v4.x=fmaxf(acc[r][0]+bi,0.f)*a+c2;
            v4.y=fmaxf(acc[r][1]+bi,0.f)*a+c2;
            v4.z=fmaxf(acc[r][2]+bi,0.f)*a+c2;
            v4.w=fmaxf(acc[r][3]+bi,0.f)*a+c2;
            *reinterpret_cast<float4*>(po + r*TDIM) = v4;
        }
    }
}

// inner dilated conv: one scale plane per block. grid (5, 32, S), block (32,8)
__global__ __launch_bounds__(256) void k_iconv(
    int j, const float* __restrict__ o1,
    const float* __restrict__ plPrev, float* __restrict__ plOut,
    const float* __restrict__ cwj, const float* __restrict__ cbj,
    const float* __restrict__ ibnj)
{
    __shared__ float sm[16][2][68];   // parity-deinterleaved, 66 used + 2 pad
    const int s = blockIdx.z, b = blockIdx.y, t0 = blockIdx.x*128;
    const int lane = threadIdx.x, o = lane&15, par = lane>>4;
    const int yb = threadIdx.y*8;
    const int tid = threadIdx.y*32 + lane;

    const float* src;
    if (j == 0)      src = o1 + ((long long)b*128 + (s==0?112:0))*TDIM;
    else if (s <= j) src = plPrev + (long long)(s*BATCH + b)*PLANE;
    else             src = o1 + ((long long)b*128 + j*16)*TDIM;

    float rw[48];
    #pragma unroll
    for (int q=0;q<48;++q) rw[q]=__ldg(cwj + o*48 + q);
    const float cb0=__ldg(cbj+o);
    float g=ibnj[o], be=ibnj[16+o], mm=ibnj[32+o], vv=ibnj[48+o];
    float bnA=g*rsqrtf(vv+1e-5f), bnB=be-mm*bnA;

    for (int idx=tid; idx<16*132; idx+=256){
        int ii=idx/132, w=idx-ii*132, t=t0-2+w;
        sm[ii][w&1][w>>1] = (t>=0 && t<TDIM) ? src[ii*TDIM+t] : 0.f;
    }
    __syncthreads();

    // thread outputs: t = t0 + 2*(yb+x) + par, x=0..7
    // tap k uses parity-row index yb + x + k  (k=0..2)
    float acc[8];
    #pragma unroll
    for (int x=0;x<8;++x) acc[x]=cb0;
    #pragma unroll
    for (int i=0;i<16;++i){
        float4 va = *reinterpret_cast<const float4*>(&sm[i][par][yb]);
        float4 vb = *reinterpret_cast<const float4*>(&sm[i][par][yb+4]);
        float2 vc = *reinterpret_cast<const float2*>(&sm[i][par][yb+8]);
        float v[10]={va.x,va.y,va.z,va.w,vb.x,vb.y,vb.z,vb.w,vc.x,vc.y};
        #pragma unroll
        for (int k=0;k<3;++k){
            float wv=rw[i*3+k];
            #pragma unroll
            for (int x=0;x<8;++x) acc[x]=fmaf(wv,v[x+k],acc[x]);
        }
    }
    float* dst = plOut + (long long)(s*BATCH + b)*PLANE + o*TDIM;
    #pragma unroll
    for (int x=0;x<8;++x){
        int t = t0 + 2*(yb + x) + par;
        if (t < TDIM) dst[t] = fmaxf(acc[x],0.f)*bnA + bnB;
    }
}

// weighted scale-sum: o2 rows [16j,16j+16) = sum_s ws[j][s] * plane_s(step j)
struct WSP { const float* w[7]; };
__global__ __launch_bounds__(256) void k_wsum(
    const float* __restrict__ pl, WSP wsp, float* __restrict__ o2)
{
    const int b = blockIdx.x, j = blockIdx.y, tid = threadIdx.x;
    const int off = j*(j+3)/2;     // plane-slot base of step j
    const int S = j+2;
    float w[8];
    #pragma unroll
    for (int s=0;s<8;++s) w[s] = (s<S) ? __ldg(wsp.w[j]+s) : 0.f;
    const float* base = pl + (long long)off*PSLOT + (long long)b*PLANE;
    float* dst = o2 + ((long long)b*128 + j*16)*TDIM;
    for (int idx=tid; idx<16*TDIM; idx+=256){
        float acc = 0.f;
        #pragma unroll
        for (int s=0;s<8;++s)
            if (s<S) acc = fmaf(w[s], base[(long long)s*PSLOT + idx], acc);
        dst[idx] = acc;
    }
}

__global__ __launch_bounds__(256) void k_se(
    const float* __restrict__ o3,
    const float* __restrict__ s1w, const float* __restrict__ s1b,
    const float* __restrict__ s2w, const float* __restrict__ s2b,
    float* __restrict__ seo)
{
    const int b=blockIdx.x, tid=threadIdx.x, w=tid>>5, lane=tid&31;
    __shared__ float m[128], s1[16];
    for (int c=w;c<128;c+=8){
        const float* p = o3 + ((long long)b*128+c)*TDIM;
        float s=0.f;
        for (int t=lane;t<TDIM;t+=32) s+=p[t];
        #pragma unroll
        for (int off=16;off;off>>=1) s+=__shfl_down_sync(0xffffffffu,s,off);
        if (!lane) m[c]=s*(1.f/600.f);
    }
    __syncthreads();
    if (tid<16){
        float s=s1b[tid];
        for (int c=0;c<128;++c) s=fmaf(s1w[tid*128+c],m[c],s);
        s1[tid]=fmaxf(s,0.f);
    }
    __syncthreads();
    if (tid<128){
        float s=s2b[tid];
        #pragma unroll
        for (int oo=0;oo<16;++oo) s=fmaf(s2w[tid*16+oo],s1[oo],s);
        seo[b*128+tid]=1.f/(1.f+expf(-s));
    }
}

__global__ __launch_bounds__(128) void k_apply(
    const float* __restrict__ o3, const float* __restrict__ se,
    const float* __restrict__ xi, const float* spPrev,
    const float* __restrict__ obn, const float* __restrict__ fbn, int gcBase,
    float* spOut, float* __restrict__ pooled)
{
    const int c=blockIdx.x, b=blockIdx.y, tid=threadIdx.x;
    const int gc=gcBase+c;
    float oA=obn[c]*rsqrtf(obn[384+c]+1e-5f);
    float oB=obn[128+c]-obn[256+c]*oA;
    float fA=fbn[gc]*rsqrtf(fbn[3072+gc]+1e-5f);
    float fB=fbn[1024+gc]-fbn[2048+gc]*fA;
    float sc=se[b*128+c];
    const float* p3 = o3 + ((long long)b*128+c)*TDIM;
    const float* px = xi + (long long)b*1024*TDIM + (long long)c*TDIM;
    const float* pp = spPrev ? spPrev + ((long long)b*128+c)*TDIM : nullptr;
    float* po = spOut + ((long long)b*128+c)*TDIM;
    float s=0.f;
    for (int t=tid;t<TDIM;t+=128){
        float r = px[t] + (pp ? pp[t] : 0.f);
        float v = p3[t]*sc + r;
        float sp = fmaxf(v,0.f)*oA + oB;
        po[t]=sp;
        s += fmaxf(sp*fA+fB, 0.f);
    }
    __shared__ float red[128];
    red[tid]=s; __syncthreads();
    for (int o=64;o;o>>=1){ if(tid<o) red[tid]+=red[tid+o]; __syncthreads(); }
    if (!tid) pooled[b*1024+gc]=red[0]*(1.f/600.f);
}

__global__ __launch_bounds__(128) void k_ptail(
    const float* __restrict__ x, const float* __restrict__ fbn,
    float* __restrict__ pooled)
{
    const int c=blockIdx.x, b=blockIdx.y, tid=threadIdx.x;
    const int gc=896+c;
    float fA=fbn[gc]*rsqrtf(fbn[3072+gc]+1e-5f);
    float fB=fbn[1024+gc]-fbn[2048+gc]*fA;
    const float* px = x + ((long long)b*1024+gc)*TDIM;
    float s=0.f;
    for (int t=tid;t<TDIM;t+=128) s+=fmaxf(px[t]*fA+fB,0.f);
    __shared__ float red[128];
    red[tid]=s; __syncthreads();
    for (int o=64;o;o>>=1){ if(tid<o) red[tid]+=red[tid+o]; __syncthreads(); }
    if (!tid) pooled[b*1024+gc]=red[0]*(1.f/600.f);
}

__global__ __launch_bounds__(256) void k_fc(
    const float* __restrict__ pooled, const float* __restrict__ fcw,
    const float* __restrict__ fcb, float* __restrict__ out)
{
    const int b=blockIdx.x, tid=threadIdx.x;
    float s0=0.f, s1=0.f;
    for (int c=tid;c<1024;c+=256){
        float p=pooled[b*1024+c];
        s0=fmaf(p,fcw[c],s0);
        s1=fmaf(p,fcw[1024+c],s1);
    }
    __shared__ float r0[256], r1[256];
    r0[tid]=s0; r1[tid]=s1; __syncthreads();
    for (int o=128;o;o>>=1){ if(tid<o){r0[tid]+=r0[tid+o]; r1[tid]+=r1[tid+o];} __syncthreads(); }
    if (!tid){ out[b*2]=r0[0]+fcb[0]; out[b*2+1]=r1[0]+fcb[1]; }
}

extern "C" void kernel_launch(void* const* d_in, const int* in_sizes, int n_in,
                              void* d_out, int out_size)
{
    const float* P[25] = {nullptr};
    int n896=0, n3584=0, n114688=0, n14336=0;
    for (int i=0;i<n_in;++i){
        int s=in_sizes[i]; const float* p=(const float*)d_in[i];
        switch(s){
            case 19660800: P[0]=p; break;
            case 114688: P[n114688++?14:1]=p; break;
            case 896: P[n896==0?2:(n896==1?15:20)]=p; n896++; break;
            case 3584: P[n3584==0?3:(n3584==1?16:21)]=p; n3584++; break;
            case 37632: P[4]=p; break;
            case 784: P[5]=p; break;
            case 3136: P[6]=p; break;
            case 14: P[7]=p; break;  case 21: P[8]=p; break;
            case 28: P[9]=p; break;  case 35: P[10]=p; break;
            case 42: P[11]=p; break; case 49: P[12]=p; break;
            case 56: P[13]=p; break;
            case 14336: P[n14336++?19:17]=p; break;
            case 112: P[18]=p; break;
            case 4096: P[22]=p; break;
            case 2048: P[23]=p; break;
            case 2: P[24]=p; break;
            default: break;
        }
    }
    float *sp,*o1,*o2,*o3,*pl,*se,*pool;
    cudaGetSymbolAddress((void**)&sp, g_sp);
    cudaGetSymbolAddress((void**)&o1, g_o1);
    cudaGetSymbolAddress((void**)&o2, g_o2);
    cudaGetSymbolAddress((void**)&o3, g_o3);
    cudaGetSymbolAddress((void**)&pl, g_pl);
    cudaGetSymbolAddress((void**)&se, g_se);
    cudaGetSymbolAddress((void**)&pool, g_pool);
    float* out = (float*)d_out;

    dim3 gG(10,32);
    dim3 bI(32,8);
    static const int off[7] = {0,2,5,9,14,20,27};

    for (int i=0;i<7;++i){
        const float* xi = P[0] + (long long)i*128*TDIM;
        k_gemm<<<gG,256>>>(P[1]+i*16384, P[2]+i*128, P[3]+i*512,
                           xi, 1024LL*TDIM, i? sp:nullptr, 128LL*TDIM,
                           nullptr, 128, o1);
        for (int j=0;j<7;++j){
            k_iconv<<<dim3(5,32,j+2),bI>>>(j, o1,
                j? pl + (long long)off[j-1]*PSLOT : pl,
                pl + (long long)off[j]*PSLOT,
                P[4]+(i*7+j)*768, P[5]+(i*7+j)*16, P[6]+(i*7+j)*64);
        }
        WSP wsp;
        for (int j=0;j<7;++j) wsp.w[j] = P[7+j] + i*(j+2);
        k_wsum<<<dim3(32,7),256>>>(pl, wsp, o2);
        k_gemm<<<gG,256>>>(P[14]+i*16384, P[15]+i*128, P[16]+i*512,
                           o2, 128LL*TDIM, nullptr, 0,
                           o1, 112, o3);
        k_se<<<32,256>>>(o3, P[17]+i*2048, P[18]+i*16, P[19]+i*2048, P[20]+i*128, se);
        k_apply<<<dim3(128,32),128>>>(o3, se, xi, i? sp:nullptr,
                                      P[21]+i*512, P[22], i*128, sp, pool);
    }
    k_ptail<<<dim3(128,32),128>>>(P[0], P[22], pool);
    k_fc<<<32,256>>>(pool, P[23], P[24], out);
}

// round 5
// speedup vs baseline: 1.6269x; 1.6269x over previous
#include <cuda_runtime.h>
#include <math.h>

#define TDIM 600
#define BATCH 32
#define NBUF (BATCH*128*TDIM)
#define PLANE (16*TDIM)
#define PSLOT (BATCH*PLANE)
#define CCOLS 620
#define CHAIN_SMEM ((2*16*CCOLS + 768)*4)

__device__ __align__(1024) float g_sp[NBUF];
__device__ __align__(1024) float g_o1[NBUF];
__device__ __align__(1024) float g_o2[NBUF];
__device__ __align__(1024) float g_o3[NBUF];
__device__ __align__(1024) float g_pl[35*PSLOT];
__device__ float g_se[BATCH*128];
__device__ float g_pool[BATCH*1024];

__global__ __launch_bounds__(256) void k_gemm(
    const float* __restrict__ W, const float* __restrict__ bias,
    const float* __restrict__ bn,
    const float* __restrict__ inA, long long aStr,
    const float* __restrict__ inB, long long bStr,
    const float* __restrict__ tail, int kTail,
    float* __restrict__ out)
{
    __shared__ float Ws[32][132];
    __shared__ float Bs[32][68];
    __shared__ float sA[128], sBb[128], sBi[128];
    const int b = blockIdx.y, t0 = blockIdx.x*64, tid = threadIdx.x;

    if (tid < 128) {
        float g=bn[tid], be=bn[128+tid], mm=bn[256+tid], vv=bn[384+tid];
        float a = g*rsqrtf(vv+1e-5f);
        sA[tid]=a; sBb[tid]=be-mm*a; sBi[tid]=bias[tid];
    }
    const float* pA = inA + (long long)b*aStr;
    const float* pB = inB ? inB + (long long)b*bStr : nullptr;
    const float* pT = tail ? tail + (long long)b*(128*TDIM) : nullptr;

    float acc[8][4];
    #pragma unroll
    for (int r=0;r<8;++r){ acc[r][0]=acc[r][1]=acc[r][2]=acc[r][3]=0.f; }
    const int tx = tid&15, ty = tid>>4;
    const int cBase = tx*4, rBase = ty*8;

    for (int k0=0;k0<128;k0+=32){
        __syncthreads();
        #pragma unroll
        for (int it=0;it<4;++it){
            int idx=it*256+tid, mo=idx>>3, kg=(idx&7)<<2;
            float4 w4 = *reinterpret_cast<const float4*>(W + mo*128 + k0 + kg);
            Ws[kg+0][mo]=w4.x; Ws[kg+1][mo]=w4.y; Ws[kg+2][mo]=w4.z; Ws[kg+3][mo]=w4.w;
        }
        #pragma unroll
        for (int it=0;it<2;++it){
            int idx=it*256+tid, kk=idx>>4, cg=(idx&15)<<2;
            int k=k0+kk, t=t0+cg;
            const float* src = (k>=kTail)? (pT + k*TDIM) : (pA + (long long)k*TDIM);
            bool addB = pB && (k<kTail);
            float4 v4;
            if (t+3 < TDIM){
                v4 = *reinterpret_cast<const float4*>(src + t);
                if (addB){
                    float4 u = *reinterpret_cast<const float4*>(pB + (long long)k*TDIM + t);
                    v4.x+=u.x; v4.y+=u.y; v4.z+=u.z; v4.w+=u.w;
                }
            } else {
                float tmp[4];
                #pragma unroll
                for (int q=0;q<4;++q){
                    int tt=t+q; float xv=0.f;
                    if (tt<TDIM){ xv=src[tt]; if(addB) xv+=pB[(long long)k*TDIM+tt]; }
                    tmp[q]=xv;
                }
                v4 = make_float4(tmp[0],tmp[1],tmp[2],tmp[3]);
            }
            *reinterpret_cast<float4*>(&Bs[kk][cg]) = v4;
        }
        __syncthreads();
        #pragma unroll
        for (int kk=0;kk<32;++kk){
            float4 a0=*reinterpret_cast<const float4*>(&Ws[kk][rBase]);
            float4 a1=*reinterpret_cast<const float4*>(&Ws[kk][rBase+4]);
            float4 bv=*reinterpret_cast<const float4*>(&Bs[kk][cBase]);
            float av[8]={a0.x,a0.y,a0.z,a0.w,a1.x,a1.y,a1.z,a1.w};
            float bb[4]={bv.x,bv.y,bv.z,bv.w};
            #pragma unroll
            for (int r=0;r<8;++r)
                #pragma unroll
                for (int q=0;q<4;++q)
                    acc[r][q]=fmaf(av[r],bb[q],acc[r][q]);
        }
    }
    if (t0+cBase+3 < TDIM){
        float* po = out + ((long long)b*128 + rBase)*TDIM + t0 + cBase;
        #pragma unroll
        for (int r=0;r<8;++r){
            int o=rBase+r; float a=sA[o], c2=sBb[o], bi=sBi[o];
            float4 v4;
            v4.x=fmaxf(acc[r][0]+bi,0.f)*a+c2;
            v4.y=fmaxf(acc[r][1]+bi,0.f)*a+c2;
            v4.z=fmaxf(acc[r][2]+bi,0.f)*a+c2;
            v4.w=fmaxf(acc[r][3]+bi,0.f)*a+c2;
            *reinterpret_cast<float4*>(po + r*TDIM) = v4;
        }
    }
}

// Fused inner-conv chain: one block per (batch b, plane s); runs steps
// j = max(0,s-1)..6 ping-ponging the 16ch x T plane in shared memory.
// grid (32, 8) -> blockIdx.x = b, blockIdx.y = s. block = 256 threads.
__global__ __launch_bounds__(256) void k_chain(
    const float* __restrict__ o1,
    const float* __restrict__ cw,   // 7*768 (this outer block)
    const float* __restrict__ cb,   // 7*16
    const float* __restrict__ ibn,  // 7*64
    float* __restrict__ pl)
{
    extern __shared__ float csm[];
    float* bufA = csm;
    float* bufB = csm + 16*CCOLS;
    float* wsm  = csm + 32*CCOLS;

    const int b = blockIdx.x, s = blockIdx.y;
    const int tid = threadIdx.x;
    const int o = tid & 15, g = tid >> 4;
    const int j0 = (s == 0) ? 0 : s - 1;
    const int srcRow = (s == 0) ? 112 : (s - 1) * 16;
    const float* src = o1 + ((long long)b*128 + srcRow)*TDIM;

    // zero halo columns (0..3 and 604..619) of both buffers
    for (int idx = tid; idx < 16*20*2; idx += 256) {
        int bsel = idx >= 16*20;
        int rem  = idx - bsel*16*20;
        int r = rem / 20, hc = rem - r*20;
        int c = (hc < 4) ? hc : 600 + hc;
        (bsel ? bufB : bufA)[r*CCOLS + c] = 0.f;
    }
    // load initial plane
    for (int idx = tid; idx < 16*TDIM; idx += 256) {
        int r = idx / TDIM, t = idx - r*TDIM;
        bufA[r*CCOLS + 4 + t] = src[idx];
    }

    float* cur = bufA;
    float* nxt = bufB;

    for (int j = j0; j < 7; ++j) {
        __syncthreads();                      // plane ready / prev weights consumed
        const float* cwj = cw + j*768;
        for (int idx = tid; idx < 768; idx += 256) wsm[idx] = cwj[idx];
        __syncthreads();

        float rw[48];
        #pragma unroll
        for (int q = 0; q < 12; ++q)
            *reinterpret_cast<float4*>(&rw[q*4]) =
                *reinterpret_cast<const float4*>(&wsm[o*48 + q*4]);
        const float cb0 = __ldg(cb + j*16 + o);
        const float* ib = ibn + j*64;
        float gg=__ldg(ib+o), be=__ldg(ib+16+o), mm=__ldg(ib+32+o), vv=__ldg(ib+48+o);
        float bnA = gg*rsqrtf(vv+1e-5f), bnB = be - mm*bnA;

        // conv: each thread -> channel o, 8 outputs per pass at tb = g*8 + 128p
        #pragma unroll
        for (int p = 0; p < 5; ++p) {
            int tb = g*8 + 128*p;
            if (tb < TDIM) {
                float acc[8];
                #pragma unroll
                for (int x=0;x<8;++x) acc[x]=cb0;
                #pragma unroll
                for (int i=0;i<16;++i){
                    const float* row = cur + i*CCOLS + tb;   // col tb == time tb-4
                    float v[16];
                    #pragma unroll
                    for (int q=0;q<4;++q)
                        *reinterpret_cast<float4*>(&v[q*4]) =
                            *reinterpret_cast<const float4*>(row + q*4);
                    #pragma unroll
                    for (int k=0;k<3;++k){
                        float wv = rw[i*3+k];
                        #pragma unroll
                        for (int x=0;x<8;++x)
                            acc[x] = fmaf(wv, v[x + 2 + 2*k], acc[x]);
                    }
                }
                float* orow = nxt + o*CCOLS + 4 + tb;
                #pragma unroll
                for (int x=0;x<8;++x)
                    orow[x] = fmaxf(acc[x],0.f)*bnA + bnB;
            }
        }
        __syncthreads();
        // coalesced copy of the step-j output plane to gmem for the wsum pass
        const int slot = j*(j+3)/2 + s;
        float* dst = pl + (long long)slot*PSLOT + (long long)b*PLANE;
        for (int idx = tid; idx < 16*TDIM; idx += 256) {
            int r = idx / TDIM, t = idx - r*TDIM;
            dst[idx] = nxt[r*CCOLS + 4 + t];
        }
        float* tmp = cur; cur = nxt; nxt = tmp;
    }
}

// weighted scale-sum: o2 rows [16j,16j+16) = sum_s ws[j][s] * plane_s(step j)
struct WSP { const float* w[7]; };
__global__ __launch_bounds__(256) void k_wsum(
    const float* __restrict__ pl, WSP wsp, float* __restrict__ o2)
{
    const int b = blockIdx.x, j = blockIdx.y, tid = threadIdx.x;
    const int off = j*(j+3)/2;
    const int S = j+2;
    float w[8];
    #pragma unroll
    for (int s=0;s<8;++s) w[s] = (s<S) ? __ldg(wsp.w[j]+s) : 0.f;
    const float* base = pl + (long long)off*PSLOT + (long long)b*PLANE;
    float* dst = o2 + ((long long)b*128 + j*16)*TDIM;
    for (int idx=tid; idx<16*TDIM; idx+=256){
        float acc = 0.f;
        #pragma unroll
        for (int s=0;s<8;++s)
            if (s<S) acc = fmaf(w[s], base[(long long)s*PSLOT + idx], acc);
        dst[idx] = acc;
    }
}

__global__ __launch_bounds__(256) void k_se(
    const float* __restrict__ o3,
    const float* __restrict__ s1w, const float* __restrict__ s1b,
    const float* __restrict__ s2w, const float* __restrict__ s2b,
    float* __restrict__ seo)
{
    const int b=blockIdx.x, tid=threadIdx.x, w=tid>>5, lane=tid&31;
    __shared__ float m[128], s1[16];
    for (int c=w;c<128;c+=8){
        const float* p = o3 + ((long long)b*128+c)*TDIM;
        float s=0.f;
        for (int t=lane;t<TDIM;t+=32) s+=p[t];
        #pragma unroll
        for (int off=16;off;off>>=1) s+=__shfl_down_sync(0xffffffffu,s,off);
        if (!lane) m[c]=s*(1.f/600.f);
    }
    __syncthreads();
    if (tid<16){
        float s=s1b[tid];
        for (int c=0;c<128;++c) s=fmaf(s1w[tid*128+c],m[c],s);
        s1[tid]=fmaxf(s,0.f);
    }
    __syncthreads();
    if (tid<128){
        float s=s2b[tid];
        #pragma unroll
        for (int oo=0;oo<16;++oo) s=fmaf(s2w[tid*16+oo],s1[oo],s);
        seo[b*128+tid]=1.f/(1.f+expf(-s));
    }
}

__global__ __launch_bounds__(128) void k_apply(
    const float* __restrict__ o3, const float* __restrict__ se,
    const float* __restrict__ xi, const float* spPrev,
    const float* __restrict__ obn, const float* __restrict__ fbn, int gcBase,
    float* spOut, float* __restrict__ pooled)
{
    const int c=blockIdx.x, b=blockIdx.y, tid=threadIdx.x;
    const int gc=gcBase+c;
    float oA=obn[c]*rsqrtf(obn[384+c]+1e-5f);
    float oB=obn[128+c]-obn[256+c]*oA;
    float fA=fbn[gc]*rsqrtf(fbn[3072+gc]+1e-5f);
    float fB=fbn[1024+gc]-fbn[2048+gc]*fA;
    float sc=se[b*128+c];
    const float* p3 = o3 + ((long long)b*128+c)*TDIM;
    const float* px = xi + (long long)b*1024*TDIM + (long long)c*TDIM;
    const float* pp = spPrev ? spPrev + ((long long)b*128+c)*TDIM : nullptr;
    float* po = spOut + ((long long)b*128+c)*TDIM;
    float s=0.f;
    for (int t=tid;t<TDIM;t+=128){
        float r = px[t] + (pp ? pp[t] : 0.f);
        float v = p3[t]*sc + r;
        float sp = fmaxf(v,0.f)*oA + oB;
        po[t]=sp;
        s += fmaxf(sp*fA+fB, 0.f);
    }
    __shared__ float red[128];
    red[tid]=s; __syncthreads();
    for (int o=64;o;o>>=1){ if(tid<o) red[tid]+=red[tid+o]; __syncthreads(); }
    if (!tid) pooled[b*1024+gc]=red[0]*(1.f/600.f);
}

__global__ __launch_bounds__(128) void k_ptail(
    const float* __restrict__ x, const float* __restrict__ fbn,
    float* __restrict__ pooled)
{
    const int c=blockIdx.x, b=blockIdx.y, tid=threadIdx.x;
    const int gc=896+c;
    float fA=fbn[gc]*rsqrtf(fbn[3072+gc]+1e-5f);
    float fB=fbn[1024+gc]-fbn[2048+gc]*fA;
    const float* px = x + ((long long)b*1024+gc)*TDIM;
    float s=0.f;
    for (int t=tid;t<TDIM;t+=128) s+=fmaxf(px[t]*fA+fB,0.f);
    __shared__ float red[128];
    red[tid]=s; __syncthreads();
    for (int o=64;o;o>>=1){ if(tid<o) red[tid]+=red[tid+o]; __syncthreads(); }
    if (!tid) pooled[b*1024+gc]=red[0]*(1.f/600.f);
}

__global__ __launch_bounds__(256) void k_fc(
    const float* __restrict__ pooled, const float* __restrict__ fcw,
    const float* __restrict__ fcb, float* __restrict__ out)
{
    const int b=blockIdx.x, tid=threadIdx.x;
    float s0=0.f, s1=0.f;
    for (int c=tid;c<1024;c+=256){
        float p=pooled[b*1024+c];
        s0=fmaf(p,fcw[c],s0);
        s1=fmaf(p,fcw[1024+c],s1);
    }
    __shared__ float r0[256], r1[256];
    r0[tid]=s0; r1[tid]=s1; __syncthreads();
    for (int o=128;o;o>>=1){ if(tid<o){r0[tid]+=r0[tid+o]; r1[tid]+=r1[tid+o];} __syncthreads(); }
    if (!tid){ out[b*2]=r0[0]+fcb[0]; out[b*2+1]=r1[0]+fcb[1]; }
}

extern "C" void kernel_launch(void* const* d_in, const int* in_sizes, int n_in,
                              void* d_out, int out_size)
{
    const float* P[25] = {nullptr};
    int n896=0, n3584=0, n114688=0, n14336=0;
    for (int i=0;i<n_in;++i){
        int s=in_sizes[i]; const float* p=(const float*)d_in[i];
        switch(s){
            case 19660800: P[0]=p; break;
            case 114688: P[n114688++?14:1]=p; break;
            case 896: P[n896==0?2:(n896==1?15:20)]=p; n896++; break;
            case 3584: P[n3584==0?3:(n3584==1?16:21)]=p; n3584++; break;
            case 37632: P[4]=p; break;
            case 784: P[5]=p; break;
            case 3136: P[6]=p; break;
            case 14: P[7]=p; break;  case 21: P[8]=p; break;
            case 28: P[9]=p; break;  case 35: P[10]=p; break;
            case 42: P[11]=p; break; case 49: P[12]=p; break;
            case 56: P[13]=p; break;
            case 14336: P[n14336++?19:17]=p; break;
            case 112: P[18]=p; break;
            case 4096: P[22]=p; break;
            case 2048: P[23]=p; break;
            case 2: P[24]=p; break;
            default: break;
        }
    }
    float *sp,*o1,*o2,*o3,*pl,*se,*pool;
    cudaGetSymbolAddress((void**)&sp, g_sp);
    cudaGetSymbolAddress((void**)&o1, g_o1);
    cudaGetSymbolAddress((void**)&o2, g_o2);
    cudaGetSymbolAddress((void**)&o3, g_o3);
    cudaGetSymbolAddress((void**)&pl, g_pl);
    cudaGetSymbolAddress((void**)&se, g_se);
    cudaGetSymbolAddress((void**)&pool, g_pool);
    float* out = (float*)d_out;

    cudaFuncSetAttribute(k_chain, cudaFuncAttributeMaxDynamicSharedMemorySize, CHAIN_SMEM);

    dim3 gG(10,32);
    for (int i=0;i<7;++i){
        const float* xi = P[0] + (long long)i*128*TDIM;
        k_gemm<<<gG,256>>>(P[1]+i*16384, P[2]+i*128, P[3]+i*512,
                           xi, 1024LL*TDIM, i? sp:nullptr, 128LL*TDIM,
                           nullptr, 128, o1);
        k_chain<<<dim3(32,8),256,CHAIN_SMEM>>>(o1,
            P[4]+i*7*768, P[5]+i*7*16, P[6]+i*7*64, pl);
        WSP wsp;
        for (int j=0;j<7;++j) wsp.w[j] = P[7+j] + i*(j+2);
        k_wsum<<<dim3(32,7),256>>>(pl, wsp, o2);
        k_gemm<<<gG,256>>>(P[14]+i*16384, P[15]+i*128, P[16]+i*512,
                           o2, 128LL*TDIM, nullptr, 0,
                           o1, 112, o3);
        k_se<<<32,256>>>(o3, P[17]+i*2048, P[18]+i*16, P[19]+i*2048, P[20]+i*128, se);
        k_apply<<<dim3(128,32),128>>>(o3, se, xi, i? sp:nullptr,
                                      P[21]+i*512, P[22], i*128, sp, pool);
    }
    k_ptail<<<dim3(128,32),128>>>(P[0], P[22], pool);
    k_fc<<<32,256>>>(pool, P[23], P[24], out);
}

// round 6
// speedup vs baseline: 1.8131x; 1.1145x over previous
#include <cuda_runtime.h>
#include <math.h>

#define TDIM 600
#define BATCH 32
#define NBUF (BATCH*128*TDIM)
#define PLANE (16*TDIM)
#define PSLOT (BATCH*PLANE)
#define CCOLS 620
#define CHAIN_SMEM ((2*16*CCOLS + 768)*4)

typedef unsigned long long u64;

__device__ __forceinline__ u64 dup2(float a){
    u64 r; asm("mov.b64 %0, {%1, %1};" : "=l"(r) : "f"(a)); return r;
}
__device__ __forceinline__ void upk2(u64 v, float& a, float& b){
    asm("mov.b64 {%0, %1}, %2;" : "=f"(a), "=f"(b) : "l"(v));
}
__device__ __forceinline__ u64 f2fma(u64 a, u64 b, u64 c){
    u64 d; asm("fma.rn.f32x2 %0, %1, %2, %3;" : "=l"(d) : "l"(a), "l"(b), "l"(c)); return d;
}

__device__ __align__(1024) float g_sp[NBUF];
__device__ __align__(1024) float g_o1[NBUF];
__device__ __align__(1024) float g_o2[NBUF];
__device__ __align__(1024) float g_o3[NBUF];
__device__ __align__(1024) float g_pl[35*PSLOT];
__device__ float g_se[BATCH*128];
__device__ float g_pool[BATCH*1024];

__global__ __launch_bounds__(256) void k_gemm(
    const float* __restrict__ W, const float* __restrict__ bias,
    const float* __restrict__ bn,
    const float* __restrict__ inA, long long aStr,
    const float* __restrict__ inB, long long bStr,
    const float* __restrict__ tail, int kTail,
    float* __restrict__ out)
{
    __shared__ float Ws[32][132];
    __shared__ float Bs[32][68];
    __shared__ float sA[128], sBb[128], sBi[128];
    const int b = blockIdx.y, t0 = blockIdx.x*64, tid = threadIdx.x;

    if (tid < 128) {
        float g=bn[tid], be=bn[128+tid], mm=bn[256+tid], vv=bn[384+tid];
        float a = g*rsqrtf(vv+1e-5f);
        sA[tid]=a; sBb[tid]=be-mm*a; sBi[tid]=bias[tid];
    }
    const float* pA = inA + (long long)b*aStr;
    const float* pB = inB ? inB + (long long)b*bStr : nullptr;
    const float* pT = tail ? tail + (long long)b*(128*TDIM) : nullptr;

    // acc2[rr][q] packs rows (rBase+2rr, rBase+2rr+1), col cBase+q
    u64 acc2[4][4];
    #pragma unroll
    for (int rr=0;rr<4;++rr)
        #pragma unroll
        for (int q=0;q<4;++q) acc2[rr][q]=0ull;

    const int tx = tid&15, ty = tid>>4;
    const int cBase = tx*4, rBase = ty*8;

    for (int k0=0;k0<128;k0+=32){
        __syncthreads();
        #pragma unroll
        for (int it=0;it<4;++it){
            int idx=it*256+tid, mo=idx>>3, kg=(idx&7)<<2;
            float4 w4 = *reinterpret_cast<const float4*>(W + mo*128 + k0 + kg);
            Ws[kg+0][mo]=w4.x; Ws[kg+1][mo]=w4.y; Ws[kg+2][mo]=w4.z; Ws[kg+3][mo]=w4.w;
        }
        #pragma unroll
        for (int it=0;it<2;++it){
            int idx=it*256+tid, kk=idx>>4, cg=(idx&15)<<2;
            int k=k0+kk, t=t0+cg;
            const float* src = (k>=kTail)? (pT + k*TDIM) : (pA + (long long)k*TDIM);
            bool addB = pB && (k<kTail);
            float4 v4;
            if (t+3 < TDIM){
                v4 = *reinterpret_cast<const float4*>(src + t);
                if (addB){
                    float4 u = *reinterpret_cast<const float4*>(pB + (long long)k*TDIM + t);
                    v4.x+=u.x; v4.y+=u.y; v4.z+=u.z; v4.w+=u.w;
                }
            } else {
                float tmp[4];
                #pragma unroll
                for (int q=0;q<4;++q){
                    int tt=t+q; float xv=0.f;
                    if (tt<TDIM){ xv=src[tt]; if(addB) xv+=pB[(long long)k*TDIM+tt]; }
                    tmp[q]=xv;
                }
                v4 = make_float4(tmp[0],tmp[1],tmp[2],tmp[3]);
            }
            *reinterpret_cast<float4*>(&Bs[kk][cg]) = v4;
        }
        __syncthreads();
        #pragma unroll
        for (int kk=0;kk<32;++kk){
            // A row-pairs come straight out of the LDS.128 (no packing)
            ulonglong2 w01 = *reinterpret_cast<const ulonglong2*>(&Ws[kk][rBase]);
            ulonglong2 w23 = *reinterpret_cast<const ulonglong2*>(&Ws[kk][rBase+4]);
            float4 bv = *reinterpret_cast<const float4*>(&Bs[kk][cBase]);
            u64 bq[4] = {dup2(bv.x), dup2(bv.y), dup2(bv.z), dup2(bv.w)};
            u64 aq[4] = {w01.x, w01.y, w23.x, w23.y};
            #pragma unroll
            for (int rr=0;rr<4;++rr)
                #pragma unroll
                for (int q=0;q<4;++q)
                    acc2[rr][q] = f2fma(aq[rr], bq[q], acc2[rr][q]);
        }
    }
    if (t0+cBase+3 < TDIM){
        float* po = out + ((long long)b*128 + rBase)*TDIM + t0 + cBase;
        #pragma unroll
        for (int rr=0;rr<4;++rr){
            float lo[4], hi[4];
            #pragma unroll
            for (int q=0;q<4;++q) upk2(acc2[rr][q], lo[q], hi[q]);
            int o0 = rBase + 2*rr, o1 = o0 + 1;
            float a0=sA[o0], c0=sBb[o0], bi0=sBi[o0];
            float a1=sA[o1], c1=sBb[o1], bi1=sBi[o1];
            float4 v0, v1;
            v0.x=fmaxf(lo[0]+bi0,0.f)*a0+c0; v0.y=fmaxf(lo[1]+bi0,0.f)*a0+c0;
            v0.z=fmaxf(lo[2]+bi0,0.f)*a0+c0; v0.w=fmaxf(lo[3]+bi0,0.f)*a0+c0;
            v1.x=fmaxf(hi[0]+bi1,0.f)*a1+c1; v1.y=fmaxf(hi[1]+bi1,0.f)*a1+c1;
            v1.z=fmaxf(hi[2]+bi1,0.f)*a1+c1; v1.w=fmaxf(hi[3]+bi1,0.f)*a1+c1;
            *reinterpret_cast<float4*>(po + 2*rr*TDIM)     = v0;
            *reinterpret_cast<float4*>(po + (2*rr+1)*TDIM) = v1;
        }
    }
}

// Fused inner-conv chain: one block per (batch b, plane s)
__global__ __launch_bounds__(256) void k_chain(
    const float* __restrict__ o1,
    const float* __restrict__ cw,   // 7*768
    const float* __restrict__ cb,   // 7*16
    const float* __restrict__ ibn,  // 7*64
    float* __restrict__ pl)
{
    extern __shared__ float csm[];
    float* bufA = csm;
    float* bufB = csm + 16*CCOLS;
    float* wsm  = csm + 32*CCOLS;

    const int b = blockIdx.x, s = blockIdx.y;
    const int tid = threadIdx.x;
    const int o = tid & 15, g = tid >> 4;
    const int j0 = (s == 0) ? 0 : s - 1;
    const int srcRow = (s == 0) ? 112 : (s - 1) * 16;
    const float* src = o1 + ((long long)b*128 + srcRow)*TDIM;

    for (int idx = tid; idx < 16*20*2; idx += 256) {
        int bsel = idx >= 16*20;
        int rem  = idx - bsel*16*20;
        int r = rem / 20, hc = rem - r*20;
        int c = (hc < 4) ? hc : 600 + hc;
        (bsel ? bufB : bufA)[r*CCOLS + c] = 0.f;
    }
    for (int idx = tid; idx < 16*TDIM; idx += 256) {
        int r = idx / TDIM, t = idx - r*TDIM;
        bufA[r*CCOLS + 4 + t] = src[idx];
    }

    float* cur = bufA;
    float* nxt = bufB;

    for (int j = j0; j < 7; ++j) {
        __syncthreads();
        const float* cwj = cw + j*768;
        for (int idx = tid; idx < 768; idx += 256) wsm[idx] = cwj[idx];
        __syncthreads();

        float rw[48];
        #pragma unroll
        for (int q = 0; q < 12; ++q)
            *reinterpret_cast<float4*>(&rw[q*4]) =
                *reinterpret_cast<const float4*>(&wsm[o*48 + q*4]);
        const float cb0 = __ldg(cb + j*16 + o);
        const float* ib = ibn + j*64;
        float gg=__ldg(ib+o), be=__ldg(ib+16+o), mm=__ldg(ib+32+o), vv=__ldg(ib+48+o);
        float bnA = gg*rsqrtf(vv+1e-5f), bnB = be - mm*bnA;

        #pragma unroll
        for (int p = 0; p < 5; ++p) {
            int tb = g*8 + 128*p;
            if (tb < TDIM) {
                u64 acc2[4];
                u64 cbd = dup2(cb0);
                #pragma unroll
                for (int xx=0;xx<4;++xx) acc2[xx]=cbd;
                #pragma unroll
                for (int i=0;i<16;++i){
                    const float* row = cur + i*CCOLS + tb;   // col tb == time tb-4
                    ulonglong2 va = *reinterpret_cast<const ulonglong2*>(row);
                    ulonglong2 vb = *reinterpret_cast<const ulonglong2*>(row+4);
                    ulonglong2 vc = *reinterpret_cast<const ulonglong2*>(row+8);
                    ulonglong2 vd = *reinterpret_cast<const ulonglong2*>(row+12);
                    u64 v2[8] = {va.x,va.y,vb.x,vb.y,vc.x,vc.y,vd.x,vd.y};
                    #pragma unroll
                    for (int k=0;k<3;++k){
                        u64 w2 = dup2(rw[i*3+k]);
                        #pragma unroll
                        for (int xx=0;xx<4;++xx)
                            acc2[xx] = f2fma(w2, v2[xx+1+k], acc2[xx]);
                    }
                }
                float ov[8];
                #pragma unroll
                for (int xx=0;xx<4;++xx){
                    float lo, hi; upk2(acc2[xx], lo, hi);
                    ov[2*xx]   = fmaxf(lo,0.f)*bnA + bnB;
                    ov[2*xx+1] = fmaxf(hi,0.f)*bnA + bnB;
                }
                float* orow = nxt + o*CCOLS + 4 + tb;
                *reinterpret_cast<float4*>(orow)   = make_float4(ov[0],ov[1],ov[2],ov[3]);
                *reinterpret_cast<float4*>(orow+4) = make_float4(ov[4],ov[5],ov[6],ov[7]);
            }
        }
        __syncthreads();
        const int slot = j*(j+3)/2 + s;
        float* dst = pl + (long long)slot*PSLOT + (long long)b*PLANE;
        for (int idx = tid; idx < 16*TDIM; idx += 256) {
            int r = idx / TDIM, t = idx - r*TDIM;
            dst[idx] = nxt[r*CCOLS + 4 + t];
        }
        float* tmp = cur; cur = nxt; nxt = tmp;
    }
}

struct WSP { const float* w[7]; };
__global__ __launch_bounds__(256) void k_wsum(
    const float* __restrict__ pl, WSP wsp, float* __restrict__ o2)
{
    const int b = blockIdx.x, j = blockIdx.y, tid = threadIdx.x;
    const int off = j*(j+3)/2;
    const int S = j+2;
    float w[8];
    #pragma unroll
    for (int s=0;s<8;++s) w[s] = (s<S) ? __ldg(wsp.w[j]+s) : 0.f;
    const float* base = pl + (long long)off*PSLOT + (long long)b*PLANE;
    float* dst = o2 + ((long long)b*128 + j*16)*TDIM;
    for (int idx=tid; idx<16*TDIM; idx+=256){
        float acc = 0.f;
        #pragma unroll
        for (int s=0;s<8;++s)
            if (s<S) acc = fmaf(w[s], base[(long long)s*PSLOT + idx], acc);
        dst[idx] = acc;
    }
}

__global__ __launch_bounds__(256) void k_se(
    const float* __restrict__ o3,
    const float* __restrict__ s1w, const float* __restrict__ s1b,
    const float* __restrict__ s2w, const float* __restrict__ s2b,
    float* __restrict__ seo)
{
    const int b=blockIdx.x, tid=threadIdx.x, w=tid>>5, lane=tid&31;
    __shared__ float m[128], s1[16];
    for (int c=w;c<128;c+=8){
        const float* p = o3 + ((long long)b*128+c)*TDIM;
        float s=0.f;
        for (int t=lane;t<TDIM;t+=32) s+=p[t];
        #pragma unroll
        for (int off=16;off;off>>=1) s+=__shfl_down_sync(0xffffffffu,s,off);
        if (!lane) m[c]=s*(1.f/600.f);
    }
    __syncthreads();
    if (tid<16){
        float s=s1b[tid];
        for (int c=0;c<128;++c) s=fmaf(s1w[tid*128+c],m[c],s);
        s1[tid]=fmaxf(s,0.f);
    }
    __syncthreads();
    if (tid<128){
        float s=s2b[tid];
        #pragma unroll
        for (int oo=0;oo<16;++oo) s=fmaf(s2w[tid*16+oo],s1[oo],s);
        seo[b*128+tid]=1.f/(1.f+expf(-s));
    }
}

__global__ __launch_bounds__(128) void k_apply(
    const float* __restrict__ o3, const float* __restrict__ se,
    const float* __restrict__ xi, const float* spPrev,
    const float* __restrict__ obn, const float* __restrict__ fbn, int gcBase,
    float* spOut, float* __restrict__ pooled)
{
    const int c=blockIdx.x, b=blockIdx.y, tid=threadIdx.x;
    const int gc=gcBase+c;
    float oA=obn[c]*rsqrtf(obn[384+c]+1e-5f);
    float oB=obn[128+c]-obn[256+c]*oA;
    float fA=fbn[gc]*rsqrtf(fbn[3072+gc]+1e-5f);
    float fB=fbn[1024+gc]-fbn[2048+gc]*fA;
    float sc=se[b*128+c];
    const float* p3 = o3 + ((long long)b*128+c)*TDIM;
    const float* px = xi + (long long)b*1024*TDIM + (long long)c*TDIM;
    const float* pp = spPrev ? spPrev + ((long long)b*128+c)*TDIM : nullptr;
    float* po = spOut + ((long long)b*128+c)*TDIM;
    float s=0.f;
    for (int t=tid;t<TDIM;t+=128){
        float r = px[t] + (pp ? pp[t] : 0.f);
        float v = p3[t]*sc + r;
        float sp = fmaxf(v,0.f)*oA + oB;
        po[t]=sp;
        s += fmaxf(sp*fA+fB, 0.f);
    }
    __shared__ float red[128];
    red[tid]=s; __syncthreads();
    for (int o=64;o;o>>=1){ if(tid<o) red[tid]+=red[tid+o]; __syncthreads(); }
    if (!tid) pooled[b*1024+gc]=red[0]*(1.f/600.f);
}

__global__ __launch_bounds__(128) void k_ptail(
    const float* __restrict__ x, const float* __restrict__ fbn,
    float* __restrict__ pooled)
{
    const int c=blockIdx.x, b=blockIdx.y, tid=threadIdx.x;
    const int gc=896+c;
    float fA=fbn[gc]*rsqrtf(fbn[3072+gc]+1e-5f);
    float fB=fbn[1024+gc]-fbn[2048+gc]*fA;
    const float* px = x + ((long long)b*1024+gc)*TDIM;
    float s=0.f;
    for (int t=tid;t<TDIM;t+=128) s+=fmaxf(px[t]*fA+fB,0.f);
    __shared__ float red[128];
    red[tid]=s; __syncthreads();
    for (int o=64;o;o>>=1){ if(tid<o) red[tid]+=red[tid+o]; __syncthreads(); }
    if (!tid) pooled[b*1024+gc]=red[0]*(1.f/600.f);
}

__global__ __launch_bounds__(256) void k_fc(
    const float* __restrict__ pooled, const float* __restrict__ fcw,
    const float* __restrict__ fcb, float* __restrict__ out)
{
    const int b=blockIdx.x, tid=threadIdx.x;
    float s0=0.f, s1=0.f;
    for (int c=tid;c<1024;c+=256){
        float p=pooled[b*1024+c];
        s0=fmaf(p,fcw[c],s0);
        s1=fmaf(p,fcw[1024+c],s1);
    }
    __shared__ float r0[256], r1[256];
    r0[tid]=s0; r1[tid]=s1; __syncthreads();
    for (int o=128;o;o>>=1){ if(tid<o){r0[tid]+=r0[tid+o]; r1[tid]+=r1[tid+o];} __syncthreads(); }
    if (!tid){ out[b*2]=r0[0]+fcb[0]; out[b*2+1]=r1[0]+fcb[1]; }
}

extern "C" void kernel_launch(void* const* d_in, const int* in_sizes, int n_in,
                              void* d_out, int out_size)
{
    const float* P[25] = {nullptr};
    int n896=0, n3584=0, n114688=0, n14336=0;
    for (int i=0;i<n_in;++i){
        int s=in_sizes[i]; const float* p=(const float*)d_in[i];
        switch(s){
            case 19660800: P[0]=p; break;
            case 114688: P[n114688++?14:1]=p; break;
            case 896: P[n896==0?2:(n896==1?15:20)]=p; n896++; break;
            case 3584: P[n3584==0?3:(n3584==1?16:21)]=p; n3584++; break;
            case 37632: P[4]=p; break;
            case 784: P[5]=p; break;
            case 3136: P[6]=p; break;
            case 14: P[7]=p; break;  case 21: P[8]=p; break;
            case 28: P[9]=p; break;  case 35: P[10]=p; break;
            case 42: P[11]=p; break; case 49: P[12]=p; break;
            case 56: P[13]=p; break;
            case 14336: P[n14336++?19:17]=p; break;
            case 112: P[18]=p; break;
            case 4096: P[22]=p; break;
            case 2048: P[23]=p; break;
            case 2: P[24]=p; break;
            default: break;
        }
    }
    float *sp,*o1,*o2,*o3,*pl,*se,*pool;
    cudaGetSymbolAddress((void**)&sp, g_sp);
    cudaGetSymbolAddress((void**)&o1, g_o1);
    cudaGetSymbolAddress((void**)&o2, g_o2);
    cudaGetSymbolAddress((void**)&o3, g_o3);
    cudaGetSymbolAddress((void**)&pl, g_pl);
    cudaGetSymbolAddress((void**)&se, g_se);
    cudaGetSymbolAddress((void**)&pool, g_pool);
    float* out = (float*)d_out;

    cudaFuncSetAttribute(k_chain, cudaFuncAttributeMaxDynamicSharedMemorySize, CHAIN_SMEM);

    dim3 gG(10,32);
    for (int i=0;i<7;++i){
        const float* xi = P[0] + (long long)i*128*TDIM;
        k_gemm<<<gG,256>>>(P[1]+i*16384, P[2]+i*128, P[3]+i*512,
                           xi, 1024LL*TDIM, i? sp:nullptr, 128LL*TDIM,
                           nullptr, 128, o1);
        k_chain<<<dim3(32,8),256,CHAIN_SMEM>>>(o1,
            P[4]+i*7*768, P[5]+i*7*16, P[6]+i*7*64, pl);
        WSP wsp;
        for (int j=0;j<7;++j) wsp.w[j] = P[7+j] + i*(j+2);
        k_wsum<<<dim3(32,7),256>>>(pl, wsp, o2);
        k_gemm<<<gG,256>>>(P[14]+i*16384, P[15]+i*128, P[16]+i*512,
                           o2, 128LL*TDIM, nullptr, 0,
                           o1, 112, o3);
        k_se<<<32,256>>>(o3, P[17]+i*2048, P[18]+i*16, P[19]+i*2048, P[20]+i*128, se);
        k_apply<<<dim3(128,32),128>>>(o3, se, xi, i? sp:nullptr,
                                      P[21]+i*512, P[22], i*128, sp, pool);
    }
    k_ptail<<<dim3(128,32),128>>>(P[0], P[22], pool);
    k_fc<<<32,256>>>(pool, P[23], P[24], out);
}